// round 5
// baseline (speedup 1.0000x reference)
#include <cuda_runtime.h>
#include <math.h>

#define N_NODES 100000
#define E_EDGES 3200000
#define S_SAMP  1000000
#define FULLM   0xffffffffu

// ---------------- device scratch (static: no allocations allowed) ----------------
__device__ __align__(16) int   g_cnt[N_NODES];
__device__ __align__(16) int   g_off[N_NODES];
__device__ int   g_bsum[128];
__device__ int   g_tsrc[E_EDGES];
__device__ int   g_tdst[E_EDGES];
__device__ int   g_esrc[E_EDGES];         // src sorted by dst (CSR payload)
__device__ __align__(16) float g_dinv[N_NODES];
__device__ __align__(16) float g_y1[N_NODES * 8];
__device__ __align__(16) float g_y2[N_NODES * 16];
__device__ __align__(8)  float2 g_z[N_NODES];    // (y3 . Wa, y3 . Wb)
__device__ float g_sa[N_NODES];
__device__ float g_sb[N_NODES];
__device__ float2 g_cab;                  // (b3 . Wa, b3 . Wb)
__device__ int g_flags[2];                // [0]: edge_index is int32, [1]: samples is int32

// ---------------- init: zero counts + dtype detection + head constants ----------------
__global__ void k_init(const int* __restrict__ ei, const int* __restrict__ sm,
                       const float* __restrict__ b3, const float* __restrict__ Wfc) {
    int i = blockIdx.x * blockDim.x + threadIdx.x;
    if (i < N_NODES) g_cnt[i] = 0;
    if (blockIdx.x == 0) {
        if (threadIdx.x == 0) {
            g_flags[0] = 0; g_flags[1] = 0;
            float ca = 0.f, cb = 0.f;
            #pragma unroll
            for (int f = 0; f < 32; f++) { ca += b3[f] * Wfc[f]; cb += b3[f] * Wfc[32 + f]; }
            g_cab = make_float2(ca, cb);
        }
        __syncthreads();
        int e_nz = 0, s_nz = 0;
        for (int k = threadIdx.x; k < 1024; k += 256) {
            if (ei[2 * k + 1] != 0) e_nz = 1;
            if (sm[2 * k + 1] != 0) s_nz = 1;
        }
        if (e_nz) atomicOr(&g_flags[0], 1);
        if (s_nz) atomicOr(&g_flags[1], 1);
    }
}

// ---------------- edge preprocessing: count + stash as int32 ----------------
__global__ void k_count(const void* __restrict__ eip) {
    int e = blockIdx.x * blockDim.x + threadIdx.x;
    if (e >= E_EDGES) return;
    int s, d;
    if (g_flags[0]) {
        const int* p = (const int*)eip;
        s = p[e]; d = p[E_EDGES + e];
    } else {
        const long long* p = (const long long*)eip;
        s = (int)p[e]; d = (int)p[(size_t)E_EDGES + e];
    }
    g_tsrc[e] = s; g_tdst[e] = d;
    atomicAdd(&g_cnt[d], 1);
}

// ---------------- scan (+dinv): 1024 elems / 256-thread block, shuffle based ----------------
__global__ void __launch_bounds__(256) k_scanA() {
    __shared__ int ws[8];
    __shared__ int wtot;
    int t = threadIdx.x, lane = t & 31, warp = t >> 5;
    int base = blockIdx.x * 1024 + t * 4;
    int4 v = make_int4(0, 0, 0, 0);
    if (base + 3 < N_NODES) v = *(const int4*)&g_cnt[base];
    else {
        if (base + 0 < N_NODES) v.x = g_cnt[base + 0];
        if (base + 1 < N_NODES) v.y = g_cnt[base + 1];
        if (base + 2 < N_NODES) v.z = g_cnt[base + 2];
    }
    // dinv (degrees are final here)
    if (base + 3 < N_NODES) {
        float4 dv;
        dv.x = rsqrtf((float)v.x + 1.0f);
        dv.y = rsqrtf((float)v.y + 1.0f);
        dv.z = rsqrtf((float)v.z + 1.0f);
        dv.w = rsqrtf((float)v.w + 1.0f);
        *(float4*)&g_dinv[base] = dv;
    } else {
        if (base + 0 < N_NODES) g_dinv[base + 0] = rsqrtf((float)v.x + 1.0f);
        if (base + 1 < N_NODES) g_dinv[base + 1] = rsqrtf((float)v.y + 1.0f);
        if (base + 2 < N_NODES) g_dinv[base + 2] = rsqrtf((float)v.z + 1.0f);
    }
    int tsum = v.x + v.y + v.z + v.w;
    int inc = tsum;
    #pragma unroll
    for (int o = 1; o < 32; o <<= 1) {
        int u = __shfl_up_sync(FULLM, inc, o);
        if (lane >= o) inc += u;
    }
    if (lane == 31) ws[warp] = inc;
    __syncthreads();
    if (warp == 0) {
        int w = (lane < 8) ? ws[lane] : 0;
        int wi = w;
        #pragma unroll
        for (int o = 1; o < 8; o <<= 1) {
            int u = __shfl_up_sync(FULLM, wi, o);
            if (lane >= o) wi += u;
        }
        if (lane < 8) ws[lane] = wi - w;      // exclusive warp base
        if (lane == 7) wtot = wi;             // block total
    }
    __syncthreads();
    int b = ws[warp] + inc - tsum;            // exclusive thread base
    int4 o;
    o.x = b + v.x; o.y = o.x + v.y; o.z = o.y + v.z; o.w = o.z + v.w;
    if (base + 3 < N_NODES) *(int4*)&g_off[base] = o;   // inclusive (fixed in scanC)
    else {
        if (base + 0 < N_NODES) g_off[base + 0] = o.x;
        if (base + 1 < N_NODES) g_off[base + 1] = o.y;
        if (base + 2 < N_NODES) g_off[base + 2] = o.z;
    }
    if (t == 0) g_bsum[blockIdx.x] = wtot;
}

// ---------------- y1 = dinv * (x @ W1): warp-per-4-nodes streaming ----------------
// Per k-chunk: 8 weight LDS.128 loaded ONCE, applied to 4 x rows (4 LDG.128).
// Weight smem traffic amortized 4x vs warp-per-node (L1tex wavefront fix).
__global__ void __launch_bounds__(256) k_mm1(const float* __restrict__ x,
                                             const float* __restrict__ W1) {
    __shared__ float sWt[8][512];     // transposed W1 (16 KB)
    int t = threadIdx.x;
    for (int i = t; i < 4096; i += 256) {
        int k = i >> 3, o = i & 7;    // read W1 coalesced
        sWt[o][k] = W1[i];
    }
    __syncthreads();

    int warp = t >> 5, lane = t & 31;
    int n0 = blockIdx.x * 32 + warp * 4;          // 4 nodes per warp
    if (n0 >= N_NODES) return;

    const float4* x4 = (const float4*)x;
    const float4* sWt4 = (const float4*)sWt;      // sWt4[o*128 + k4]

    int nn[4];
    #pragma unroll
    for (int m = 0; m < 4; m++) {
        int n = n0 + m;
        nn[m] = (n < N_NODES) ? n : (N_NODES - 1);
    }

    float acc[4][8];
    #pragma unroll
    for (int m = 0; m < 4; m++)
        #pragma unroll
        for (int o = 0; o < 8; o++) acc[m][o] = 0.f;

    #pragma unroll
    for (int q = 0; q < 4; q++) {
        int k4 = lane + 32 * q;
        float4 w[8];
        #pragma unroll
        for (int o = 0; o < 8; o++) w[o] = sWt4[o * 128 + k4];
        #pragma unroll
        for (int m = 0; m < 4; m++) {
            float4 xv = __ldg(&x4[(size_t)nn[m] * 128 + k4]);
            #pragma unroll
            for (int o = 0; o < 8; o++) {
                acc[m][o] = fmaf(xv.x, w[o].x, acc[m][o]);
                acc[m][o] = fmaf(xv.y, w[o].y, acc[m][o]);
                acc[m][o] = fmaf(xv.z, w[o].z, acc[m][o]);
                acc[m][o] = fmaf(xv.w, w[o].w, acc[m][o]);
            }
        }
    }
    #pragma unroll
    for (int off = 16; off; off >>= 1)
        #pragma unroll
        for (int m = 0; m < 4; m++)
            #pragma unroll
            for (int o = 0; o < 8; o++)
                acc[m][o] += __shfl_xor_sync(FULLM, acc[m][o], off);

    // every lane now has all sums; lanes 0-3 store node n0+lane
    if (lane < 4) {
        int n = n0 + lane;
        if (n < N_NODES) {
            float di = g_dinv[n];
            float4* y14 = (float4*)g_y1;
            y14[n * 2 + 0] = make_float4(acc[lane][0] * di, acc[lane][1] * di,
                                         acc[lane][2] * di, acc[lane][3] * di);
            y14[n * 2 + 1] = make_float4(acc[lane][4] * di, acc[lane][5] * di,
                                         acc[lane][6] * di, acc[lane][7] * di);
        }
    }
}

// inclusive -> global exclusive; each block redundantly sums its block-prefix (<=98 values)
__global__ void __launch_bounds__(256) k_scanC() {
    int nb = blockIdx.x;                      // same 1024-range as scanA block nb
    int bbase = 0;
    for (int i = 0; i < nb; i++) bbase += g_bsum[i];
    int base = nb * 1024 + threadIdx.x * 4;
    if (base + 3 < N_NODES) {
        int4 o = *(const int4*)&g_off[base];
        int4 c = *(const int4*)&g_cnt[base];
        o.x += bbase - c.x; o.y += bbase - c.y; o.z += bbase - c.z; o.w += bbase - c.w;
        *(int4*)&g_off[base] = o;
    } else {
        for (int q = 0; q < 4; q++)
            if (base + q < N_NODES) g_off[base + q] += bbase - g_cnt[base + q];
    }
}

// ---------------- counting-sort placement (atomic cursor on g_off) ----------------
// After this kernel g_off[n] == end of bucket n; layers use e0 = g_off[n] - g_cnt[n].
__global__ void k_place() {
    int e = blockIdx.x * blockDim.x + threadIdx.x;
    if (e >= E_EDGES) return;
    int d = g_tdst[e];
    int pos = atomicAdd(&g_off[d], 1);
    g_esrc[pos] = g_tsrc[e];
}

// ---------------- Layer 1: agg(y1) -> relu -> y2 = dinv*(h1@W2) ----------------
__global__ void __launch_bounds__(256) k_layer1(const float* __restrict__ b1,
                                                const float* __restrict__ W2) {
    __shared__ float sW2[128];   // 8x16
    int t = threadIdx.x;
    if (t < 128) sW2[t] = W2[t];
    __syncthreads();
    int warp = t >> 5, lane = t & 31;
    int n = blockIdx.x * 8 + warp;
    if (n >= N_NODES) return;
    int end = g_off[n], cnt = g_cnt[n], e0 = end - cnt;
    int f = lane & 7;
    float acc = 0.f;
    for (int e = (lane >> 3); e < cnt; e += 4) {
        int s = g_esrc[e0 + e];
        acc += __ldg(&g_y1[s * 8 + f]);
    }
    acc += __shfl_down_sync(FULLM, acc, 16);
    acc += __shfl_down_sync(FULLM, acc, 8);
    float di = g_dinv[n];
    float h = 0.f;
    if (lane < 8) h = fmaxf(di * (acc + g_y1[n * 8 + lane]) + b1[lane], 0.f);
    float out = 0.f;
    int j = lane & 15;
    #pragma unroll
    for (int k = 0; k < 8; k++) {
        float hk = __shfl_sync(FULLM, h, k);
        out += hk * sW2[k * 16 + j];
    }
    if (lane < 16) g_y2[n * 16 + lane] = di * out;
}

// ---------------- Layer 2: agg(y2) -> relu -> y3 = dinv*(h2@W3), collapse to z ----------------
__global__ void __launch_bounds__(256) k_layer2(const float* __restrict__ b2,
                                                const float* __restrict__ W3,
                                                const float* __restrict__ Wfc) {
    __shared__ float sW3[512];   // 16x32
    __shared__ float sWfc[64];
    int t = threadIdx.x;
    for (int i = t; i < 512; i += 256) sW3[i] = W3[i];
    if (t < 64) sWfc[t] = Wfc[t];
    __syncthreads();
    int warp = t >> 5, lane = t & 31;
    int n = blockIdx.x * 8 + warp;
    if (n >= N_NODES) return;
    int end = g_off[n], cnt = g_cnt[n], e0 = end - cnt;
    int f = lane & 15;
    float acc = 0.f;
    for (int e = (lane >> 4); e < cnt; e += 2) {
        int s = g_esrc[e0 + e];
        acc += __ldg(&g_y2[s * 16 + f]);
    }
    acc += __shfl_down_sync(FULLM, acc, 16);
    float di = g_dinv[n];
    float h = 0.f;
    if (lane < 16) h = fmaxf(di * (acc + g_y2[n * 16 + lane]) + b2[lane], 0.f);
    float out = 0.f;
    #pragma unroll
    for (int k = 0; k < 16; k++) {
        float hk = __shfl_sync(FULLM, h, k);
        out += hk * sW3[k * 32 + lane];
    }
    float y3v = di * out;                       // y3[n][lane]
    float za = y3v * sWfc[lane];
    float zb = y3v * sWfc[32 + lane];
    #pragma unroll
    for (int o = 16; o; o >>= 1) {
        za += __shfl_xor_sync(FULLM, za, o);
        zb += __shfl_xor_sync(FULLM, zb, o);
    }
    if (lane == 0) g_z[n] = make_float2(za, zb);
}

// ---------------- Layer 3 (scalarized): sa/sb = dinv*(sum z[src] + z[n]) + cab ----------------
__global__ void __launch_bounds__(256) k_layer3() {
    int t = threadIdx.x;
    int warp = t >> 5, lane = t & 31;
    int n = blockIdx.x * 8 + warp;
    if (n >= N_NODES) return;
    int end = g_off[n], cnt = g_cnt[n], e0 = end - cnt;
    float ax = 0.f, ay = 0.f;
    for (int e = lane; e < cnt; e += 32) {
        int s = g_esrc[e0 + e];
        float2 z = __ldg(&g_z[s]);
        ax += z.x; ay += z.y;
    }
    #pragma unroll
    for (int o = 16; o; o >>= 1) {
        ax += __shfl_xor_sync(FULLM, ax, o);
        ay += __shfl_xor_sync(FULLM, ay, o);
    }
    if (lane == 0) {
        float di = g_dinv[n];
        float2 zn = g_z[n];
        g_sa[n] = di * (ax + zn.x) + g_cab.x;
        g_sb[n] = di * (ay + zn.y) + g_cab.y;
    }
}

// ---------------- Final: out[s] = sigmoid(sa[i] + sb[j] + bfc) ----------------
__global__ void __launch_bounds__(256) k_final(const void* __restrict__ smp,
                                               const float* __restrict__ bfc,
                                               float* __restrict__ out) {
    int s = blockIdx.x * 256 + threadIdx.x;
    if (s >= S_SAMP) return;
    long long i, j;
    if (g_flags[1]) {
        const int* p = (const int*)smp;
        i = p[2 * s]; j = p[2 * s + 1];
    } else {
        const long long* p = (const long long*)smp;
        i = p[2 * (size_t)s]; j = p[2 * (size_t)s + 1];
    }
    float v = __ldg(&g_sa[i]) + __ldg(&g_sb[j]) + __ldg(bfc);
    out[s] = 1.f / (1.f + __expf(-v));
}

// ---------------- launch ----------------
extern "C" void kernel_launch(void* const* d_in, const int* in_sizes, int n_in,
                              void* d_out, int out_size) {
    const float* x   = (const float*)d_in[0];
    const void*  ei  = d_in[1];
    const void*  smp = d_in[2];
    const float* W1  = (const float*)d_in[3];
    const float* b1  = (const float*)d_in[4];
    const float* W2  = (const float*)d_in[5];
    const float* b2  = (const float*)d_in[6];
    const float* W3  = (const float*)d_in[7];
    const float* b3  = (const float*)d_in[8];
    const float* Wfc = (const float*)d_in[9];
    const float* bfc = (const float*)d_in[10];
    float* out = (float*)d_out;

    const int nb_scan = (N_NODES + 1023) / 1024;   // 98

    k_init<<<(N_NODES + 255) / 256, 256>>>((const int*)ei, (const int*)smp, b3, Wfc);
    k_count<<<(E_EDGES + 255) / 256, 256>>>(ei);
    k_scanA<<<nb_scan, 256>>>();
    k_mm1<<<(N_NODES + 31) / 32, 256>>>(x, W1);    // launch #4: profiled slot
    k_scanC<<<nb_scan, 256>>>();
    k_place<<<(E_EDGES + 255) / 256, 256>>>();
    k_layer1<<<(N_NODES + 7) / 8, 256>>>(b1, W2);
    k_layer2<<<(N_NODES + 7) / 8, 256>>>(b2, W3, Wfc);
    k_layer3<<<(N_NODES + 7) / 8, 256>>>();
    k_final<<<(S_SAMP + 255) / 256, 256>>>(smp, bfc, out);
}

// round 8
// speedup vs baseline: 1.2488x; 1.2488x over previous
#include <cuda_runtime.h>
#include <math.h>

#define N_NODES 100000
#define E_EDGES 3200000
#define S_SAMP  1000000
#define FULLM   0xffffffffu

// ---------------- device scratch (static: no allocations allowed) ----------------
__device__ __align__(16) int   g_cnt[N_NODES];
__device__ __align__(16) int   g_off[N_NODES];
__device__ unsigned long long g_state[128];   // decoupled-lookback: status<<62 | value
__device__ int   g_tsrc[E_EDGES];
__device__ int   g_tdst[E_EDGES];
__device__ int   g_esrc[E_EDGES];             // src sorted by dst (CSR payload)
__device__ __align__(16) float g_dinv[N_NODES];
__device__ __align__(16) float g_y1[N_NODES * 8];
__device__ __align__(16) float g_y2[N_NODES * 16];
__device__ __align__(8)  float2 g_z[N_NODES]; // (y3 . Wa, y3 . Wb)
__device__ float g_sa[N_NODES];
__device__ float g_sb[N_NODES];
__device__ float2 g_cab;                      // (b3 . Wa, b3 . Wb)
__device__ int g_flags[2];                    // [0]: edge_index is int32, [1]: samples is int32

// ---------------- packed f32x2 helpers ----------------
__device__ __forceinline__ unsigned long long pack2(float a, float b) {
    unsigned long long r;
    asm("mov.b64 %0, {%1, %2};" : "=l"(r) : "f"(a), "f"(b));
    return r;
}
__device__ __forceinline__ float2 unpack2(unsigned long long v) {
    float2 f;
    asm("mov.b64 {%0, %1}, %2;" : "=f"(f.x), "=f"(f.y) : "l"(v));
    return f;
}
__device__ __forceinline__ void fma2v(unsigned long long& acc, unsigned long long a, unsigned long long b) {
    asm("fma.rn.f32x2 %0, %1, %2, %3;" : "=l"(acc) : "l"(a), "l"(b), "l"(acc));
}

// ---------------- init: zero counts + scan state + dtype detection + head constants ----------------
__global__ void k_init(const int* __restrict__ ei, const int* __restrict__ sm,
                       const float* __restrict__ b3, const float* __restrict__ Wfc) {
    int i = blockIdx.x * blockDim.x + threadIdx.x;
    if (i < N_NODES) g_cnt[i] = 0;
    if (i < 128) g_state[i] = 0ULL;
    if (blockIdx.x == 0) {
        if (threadIdx.x == 0) {
            g_flags[0] = 0; g_flags[1] = 0;
            float ca = 0.f, cb = 0.f;
            #pragma unroll
            for (int f = 0; f < 32; f++) { ca += b3[f] * Wfc[f]; cb += b3[f] * Wfc[32 + f]; }
            g_cab = make_float2(ca, cb);
        }
        __syncthreads();
        int e_nz = 0, s_nz = 0;
        for (int k = threadIdx.x; k < 1024; k += 256) {
            if (ei[2 * k + 1] != 0) e_nz = 1;
            if (sm[2 * k + 1] != 0) s_nz = 1;
        }
        if (e_nz) atomicOr(&g_flags[0], 1);
        if (s_nz) atomicOr(&g_flags[1], 1);
    }
}

// ---------------- edge preprocessing: count + stash as int32 ----------------
__global__ void k_count(const void* __restrict__ eip) {
    int e = blockIdx.x * blockDim.x + threadIdx.x;
    if (e >= E_EDGES) return;
    int s, d;
    if (g_flags[0]) {
        const int* p = (const int*)eip;
        s = p[e]; d = p[E_EDGES + e];
    } else {
        const long long* p = (const long long*)eip;
        s = (int)p[e]; d = (int)p[(size_t)E_EDGES + e];
    }
    g_tsrc[e] = s; g_tdst[e] = d;
    atomicAdd(&g_cnt[d], 1);
}

// ---------------- single-pass scan (decoupled lookback) + dinv ----------------
// 98 blocks x 256 threads x 4 elems. Publishes aggregate before any wait.
__global__ void __launch_bounds__(256) k_scan() {
    __shared__ int ws[8];
    __shared__ int stotal;
    __shared__ int sbase;
    int t = threadIdx.x, lane = t & 31, warp = t >> 5;
    int base = blockIdx.x * 1024 + t * 4;
    int4 v = make_int4(0, 0, 0, 0);
    if (base + 3 < N_NODES) v = *(const int4*)&g_cnt[base];
    else {
        if (base + 0 < N_NODES) v.x = g_cnt[base + 0];
        if (base + 1 < N_NODES) v.y = g_cnt[base + 1];
        if (base + 2 < N_NODES) v.z = g_cnt[base + 2];
    }
    // dinv (degrees final here)
    if (base + 3 < N_NODES) {
        float4 dv;
        dv.x = rsqrtf((float)v.x + 1.0f);
        dv.y = rsqrtf((float)v.y + 1.0f);
        dv.z = rsqrtf((float)v.z + 1.0f);
        dv.w = rsqrtf((float)v.w + 1.0f);
        *(float4*)&g_dinv[base] = dv;
    } else {
        if (base + 0 < N_NODES) g_dinv[base + 0] = rsqrtf((float)v.x + 1.0f);
        if (base + 1 < N_NODES) g_dinv[base + 1] = rsqrtf((float)v.y + 1.0f);
        if (base + 2 < N_NODES) g_dinv[base + 2] = rsqrtf((float)v.z + 1.0f);
    }
    int tsum = v.x + v.y + v.z + v.w;
    int inc = tsum;
    #pragma unroll
    for (int o = 1; o < 32; o <<= 1) {
        int u = __shfl_up_sync(FULLM, inc, o);
        if (lane >= o) inc += u;
    }
    if (lane == 31) ws[warp] = inc;
    __syncthreads();
    if (warp == 0) {
        int w = (lane < 8) ? ws[lane] : 0;
        int wi = w;
        #pragma unroll
        for (int o = 1; o < 8; o <<= 1) {
            int u = __shfl_up_sync(FULLM, wi, o);
            if (lane >= o) wi += u;
        }
        if (lane < 8) ws[lane] = wi - w;          // exclusive warp base
        if (lane == 7) {
            stotal = wi;                          // block total
            // publish AGGREGATE (status 1) immediately
            atomicExch(&g_state[blockIdx.x],
                       (1ULL << 62) | (unsigned long long)(unsigned int)wi);
        }
    }
    __syncthreads();
    if (t == 0) {
        int exc = 0;
        int p = (int)blockIdx.x - 1;
        while (p >= 0) {
            unsigned long long s;
            do { s = atomicAdd(&g_state[p], 0ULL); } while ((s >> 62) == 0ULL);
            exc += (int)(unsigned int)(s & 0xffffffffULL);
            if ((s >> 62) == 2ULL) break;         // inclusive: done
            p--;
        }
        sbase = exc;
        atomicExch(&g_state[blockIdx.x],
                   (2ULL << 62) | (unsigned long long)(unsigned int)(exc + stotal));
    }
    __syncthreads();
    int b = sbase + ws[warp] + inc - tsum;        // global exclusive base for this thread
    int4 o;
    o.x = b; o.y = b + v.x; o.z = o.y + v.y; o.w = o.z + v.z;
    if (base + 3 < N_NODES) *(int4*)&g_off[base] = o;
    else {
        if (base + 0 < N_NODES) g_off[base + 0] = o.x;
        if (base + 1 < N_NODES) g_off[base + 1] = o.y;
        if (base + 2 < N_NODES) g_off[base + 2] = o.z;
    }
}

// ---------------- counting-sort placement (atomic cursor on g_off) ----------------
// After this kernel g_off[n] == end of bucket n; layers use e0 = g_off[n] - g_cnt[n].
__global__ void k_place() {
    int e = blockIdx.x * blockDim.x + threadIdx.x;
    if (e >= E_EDGES) return;
    int d = g_tdst[e];
    int pos = atomicAdd(&g_off[d], 1);
    g_esrc[pos] = g_tsrc[e];
}

// ---------------- y1 = dinv * (x @ W1): warp-per-4-nodes, f32x2 FMA ----------------
__global__ void __launch_bounds__(256) k_mm1(const float* __restrict__ x,
                                             const float* __restrict__ W1) {
    __shared__ float sWt[8][512];     // transposed W1 (16 KB)
    int t = threadIdx.x;
    for (int i = t; i < 4096; i += 256) {
        int k = i >> 3, o = i & 7;    // read W1 coalesced
        sWt[o][k] = W1[i];
    }
    __syncthreads();

    int warp = t >> 5, lane = t & 31;
    int n0 = blockIdx.x * 32 + warp * 4;          // 4 nodes per warp
    if (n0 >= N_NODES) return;

    const float4* x4 = (const float4*)x;
    const float4* sWt4 = (const float4*)sWt;      // sWt4[o*128 + k4]

    int nn[4];
    #pragma unroll
    for (int m = 0; m < 4; m++) {
        int n = n0 + m;
        nn[m] = (n < N_NODES) ? n : (N_NODES - 1);
    }

    unsigned long long acc2[4][8];                // even-k sums in lo, odd-k in hi
    #pragma unroll
    for (int m = 0; m < 4; m++)
        #pragma unroll
        for (int o = 0; o < 8; o++) acc2[m][o] = 0ULL;

    #pragma unroll
    for (int q = 0; q < 4; q++) {
        int k4 = lane + 32 * q;
        unsigned long long wlo[8], whi[8];
        #pragma unroll
        for (int o = 0; o < 8; o++) {
            float4 wv = sWt4[o * 128 + k4];
            wlo[o] = pack2(wv.x, wv.y);
            whi[o] = pack2(wv.z, wv.w);
        }
        #pragma unroll
        for (int m = 0; m < 4; m++) {
            float4 xv = __ldg(&x4[(size_t)nn[m] * 128 + k4]);
            unsigned long long xa = pack2(xv.x, xv.y);
            unsigned long long xb = pack2(xv.z, xv.w);
            #pragma unroll
            for (int o = 0; o < 8; o++) {
                fma2v(acc2[m][o], xa, wlo[o]);
                fma2v(acc2[m][o], xb, whi[o]);
            }
        }
    }

    float acc[4][8];
    #pragma unroll
    for (int m = 0; m < 4; m++)
        #pragma unroll
        for (int o = 0; o < 8; o++) {
            float2 f = unpack2(acc2[m][o]);
            acc[m][o] = f.x + f.y;
        }

    #pragma unroll
    for (int off = 16; off; off >>= 1)
        #pragma unroll
        for (int m = 0; m < 4; m++)
            #pragma unroll
            for (int o = 0; o < 8; o++)
                acc[m][o] += __shfl_xor_sync(FULLM, acc[m][o], off);

    if (lane < 4) {
        int n = n0 + lane;
        if (n < N_NODES) {
            float di = g_dinv[n];
            float4* y14 = (float4*)g_y1;
            y14[n * 2 + 0] = make_float4(acc[lane][0] * di, acc[lane][1] * di,
                                         acc[lane][2] * di, acc[lane][3] * di);
            y14[n * 2 + 1] = make_float4(acc[lane][4] * di, acc[lane][5] * di,
                                         acc[lane][6] * di, acc[lane][7] * di);
        }
    }
}

// ---------------- Layer 1: agg(y1) -> relu -> y2 = dinv*(h1@W2) ----------------
__global__ void __launch_bounds__(256) k_layer1(const float* __restrict__ b1,
                                                const float* __restrict__ W2) {
    __shared__ float sW2[128];   // 8x16
    int t = threadIdx.x;
    if (t < 128) sW2[t] = W2[t];
    __syncthreads();
    int warp = t >> 5, lane = t & 31;
    int n = blockIdx.x * 8 + warp;
    if (n >= N_NODES) return;
    int end = g_off[n], cnt = g_cnt[n], e0 = end - cnt;
    int f = lane & 7;
    float acc = 0.f;
    for (int e = (lane >> 3); e < cnt; e += 4) {
        int s = g_esrc[e0 + e];
        acc += __ldg(&g_y1[s * 8 + f]);
    }
    acc += __shfl_down_sync(FULLM, acc, 16);
    acc += __shfl_down_sync(FULLM, acc, 8);
    float di = g_dinv[n];
    float h = 0.f;
    if (lane < 8) h = fmaxf(di * (acc + g_y1[n * 8 + lane]) + b1[lane], 0.f);
    float out = 0.f;
    int j = lane & 15;
    #pragma unroll
    for (int k = 0; k < 8; k++) {
        float hk = __shfl_sync(FULLM, h, k);
        out += hk * sW2[k * 16 + j];
    }
    if (lane < 16) g_y2[n * 16 + lane] = di * out;
}

// ---------------- Layer 2: agg(y2) -> relu -> y3 = dinv*(h2@W3), collapse to z ----------------
__global__ void __launch_bounds__(256) k_layer2(const float* __restrict__ b2,
                                                const float* __restrict__ W3,
                                                const float* __restrict__ Wfc) {
    __shared__ float sW3[512];   // 16x32
    __shared__ float sWfc[64];
    int t = threadIdx.x;
    for (int i = t; i < 512; i += 256) sW3[i] = W3[i];
    if (t < 64) sWfc[t] = Wfc[t];
    __syncthreads();
    int warp = t >> 5, lane = t & 31;
    int n = blockIdx.x * 8 + warp;
    if (n >= N_NODES) return;
    int end = g_off[n], cnt = g_cnt[n], e0 = end - cnt;
    int f = lane & 15;
    float acc = 0.f;
    for (int e = (lane >> 4); e < cnt; e += 2) {
        int s = g_esrc[e0 + e];
        acc += __ldg(&g_y2[s * 16 + f]);
    }
    acc += __shfl_down_sync(FULLM, acc, 16);
    float di = g_dinv[n];
    float h = 0.f;
    if (lane < 16) h = fmaxf(di * (acc + g_y2[n * 16 + lane]) + b2[lane], 0.f);
    float out = 0.f;
    #pragma unroll
    for (int k = 0; k < 16; k++) {
        float hk = __shfl_sync(FULLM, h, k);
        out += hk * sW3[k * 32 + lane];
    }
    float y3v = di * out;                       // y3[n][lane]
    float za = y3v * sWfc[lane];
    float zb = y3v * sWfc[32 + lane];
    #pragma unroll
    for (int o = 16; o; o >>= 1) {
        za += __shfl_xor_sync(FULLM, za, o);
        zb += __shfl_xor_sync(FULLM, zb, o);
    }
    if (lane == 0) g_z[n] = make_float2(za, zb);
}

// ---------------- Layer 3 (scalarized): sa/sb = dinv*(sum z[src] + z[n]) + cab ----------------
__global__ void __launch_bounds__(256) k_layer3() {
    int t = threadIdx.x;
    int warp = t >> 5, lane = t & 31;
    int n = blockIdx.x * 8 + warp;
    if (n >= N_NODES) return;
    int end = g_off[n], cnt = g_cnt[n], e0 = end - cnt;
    float ax = 0.f, ay = 0.f;
    for (int e = lane; e < cnt; e += 32) {
        int s = g_esrc[e0 + e];
        float2 z = __ldg(&g_z[s]);
        ax += z.x; ay += z.y;
    }
    #pragma unroll
    for (int o = 16; o; o >>= 1) {
        ax += __shfl_xor_sync(FULLM, ax, o);
        ay += __shfl_xor_sync(FULLM, ay, o);
    }
    if (lane == 0) {
        float di = g_dinv[n];
        float2 zn = g_z[n];
        g_sa[n] = di * (ax + zn.x) + g_cab.x;
        g_sb[n] = di * (ay + zn.y) + g_cab.y;
    }
}

// ---------------- Final: out[s] = sigmoid(sa[i] + sb[j] + bfc) ----------------
__global__ void __launch_bounds__(256) k_final(const void* __restrict__ smp,
                                               const float* __restrict__ bfc,
                                               float* __restrict__ out) {
    int s = blockIdx.x * 256 + threadIdx.x;
    if (s >= S_SAMP) return;
    long long i, j;
    if (g_flags[1]) {
        const int* p = (const int*)smp;
        i = p[2 * s]; j = p[2 * s + 1];
    } else {
        const long long* p = (const long long*)smp;
        i = p[2 * (size_t)s]; j = p[2 * (size_t)s + 1];
    }
    float v = __ldg(&g_sa[i]) + __ldg(&g_sb[j]) + __ldg(bfc);
    out[s] = 1.f / (1.f + __expf(-v));
}

// ---------------- launch ----------------
extern "C" void kernel_launch(void* const* d_in, const int* in_sizes, int n_in,
                              void* d_out, int out_size) {
    const float* x   = (const float*)d_in[0];
    const void*  ei  = d_in[1];
    const void*  smp = d_in[2];
    const float* W1  = (const float*)d_in[3];
    const float* b1  = (const float*)d_in[4];
    const float* W2  = (const float*)d_in[5];
    const float* b2  = (const float*)d_in[6];
    const float* W3  = (const float*)d_in[7];
    const float* b3  = (const float*)d_in[8];
    const float* Wfc = (const float*)d_in[9];
    const float* bfc = (const float*)d_in[10];
    float* out = (float*)d_out;

    const int nb_scan = (N_NODES + 1023) / 1024;   // 98

    k_init<<<(N_NODES + 255) / 256, 256>>>((const int*)ei, (const int*)smp, b3, Wfc);
    k_count<<<(E_EDGES + 255) / 256, 256>>>(ei);
    k_scan<<<nb_scan, 256>>>();
    k_place<<<(E_EDGES + 255) / 256, 256>>>();     // launch #4: profiled slot
    k_mm1<<<(N_NODES + 31) / 32, 256>>>(x, W1);
    k_layer1<<<(N_NODES + 7) / 8, 256>>>(b1, W2);
    k_layer2<<<(N_NODES + 7) / 8, 256>>>(b2, W3, Wfc);
    k_layer3<<<(N_NODES + 7) / 8, 256>>>();
    k_final<<<(S_SAMP + 255) / 256, 256>>>(smp, bfc, out);
}

// round 9
// speedup vs baseline: 1.2980x; 1.0394x over previous
#include <cuda_runtime.h>
#include <math.h>

#define N_NODES 100000
#define E_EDGES 3200000
#define S_SAMP  1000000
#define FULLM   0xffffffffu

// ---------------- device scratch (static: no allocations allowed) ----------------
__device__ __align__(16) int   g_cnt[N_NODES];
__device__ __align__(16) int   g_off[N_NODES];
__device__ unsigned long long g_state[128];   // decoupled-lookback: status<<62 | value
__device__ int   g_tsrc[E_EDGES];
__device__ int   g_tdst[E_EDGES];
__device__ int   g_esrc[E_EDGES];             // src sorted by dst (CSR payload)
__device__ __align__(16) float g_dinv[N_NODES];
__device__ __align__(16) float g_y1[N_NODES * 8];
__device__ __align__(16) float g_y2[N_NODES * 16];
__device__ __align__(8)  float2 g_z[N_NODES]; // (y3 . Wa, y3 . Wb)
__device__ float g_sa[N_NODES];
__device__ float g_sb[N_NODES];
__device__ float2 g_cab;                      // (b3 . Wa, b3 . Wb)
__device__ int g_flags[2];                    // [0]: edge_index is int32, [1]: samples is int32

// ---------------- packed f32x2 helpers ----------------
__device__ __forceinline__ unsigned long long pack2(float a, float b) {
    unsigned long long r;
    asm("mov.b64 %0, {%1, %2};" : "=l"(r) : "f"(a), "f"(b));
    return r;
}
__device__ __forceinline__ float2 unpack2(unsigned long long v) {
    float2 f;
    asm("mov.b64 {%0, %1}, %2;" : "=f"(f.x), "=f"(f.y) : "l"(v));
    return f;
}
__device__ __forceinline__ void fma2v(unsigned long long& acc, unsigned long long a, unsigned long long b) {
    asm("fma.rn.f32x2 %0, %1, %2, %3;" : "=l"(acc) : "l"(a), "l"(b), "l"(acc));
}

// ---------------- init: zero counts + scan state + dtype detection + head constants ----------------
__global__ void k_init(const int* __restrict__ ei, const int* __restrict__ sm,
                       const float* __restrict__ b3, const float* __restrict__ Wfc) {
    int i = blockIdx.x * blockDim.x + threadIdx.x;
    if (i < N_NODES) g_cnt[i] = 0;
    if (i < 128) g_state[i] = 0ULL;
    if (blockIdx.x == 0) {
        if (threadIdx.x == 0) {
            g_flags[0] = 0; g_flags[1] = 0;
            float ca = 0.f, cb = 0.f;
            #pragma unroll
            for (int f = 0; f < 32; f++) { ca += b3[f] * Wfc[f]; cb += b3[f] * Wfc[32 + f]; }
            g_cab = make_float2(ca, cb);
        }
        __syncthreads();
        int e_nz = 0, s_nz = 0;
        for (int k = threadIdx.x; k < 1024; k += 256) {
            if (ei[2 * k + 1] != 0) e_nz = 1;
            if (sm[2 * k + 1] != 0) s_nz = 1;
        }
        if (e_nz) atomicOr(&g_flags[0], 1);
        if (s_nz) atomicOr(&g_flags[1], 1);
    }
}

// ---------------- edge preprocessing: count + stash as int32 ----------------
__global__ void k_count(const void* __restrict__ eip) {
    int e = blockIdx.x * blockDim.x + threadIdx.x;
    if (e >= E_EDGES) return;
    int s, d;
    if (g_flags[0]) {
        const int* p = (const int*)eip;
        s = p[e]; d = p[E_EDGES + e];
    } else {
        const long long* p = (const long long*)eip;
        s = (int)p[e]; d = (int)p[(size_t)E_EDGES + e];
    }
    g_tsrc[e] = s; g_tdst[e] = d;
    atomicAdd(&g_cnt[d], 1);
}

// ---------------- single-pass scan (decoupled lookback) + dinv ----------------
__global__ void __launch_bounds__(256) k_scan() {
    __shared__ int ws[8];
    __shared__ int stotal;
    __shared__ int sbase;
    int t = threadIdx.x, lane = t & 31, warp = t >> 5;
    int base = blockIdx.x * 1024 + t * 4;
    int4 v = make_int4(0, 0, 0, 0);
    if (base + 3 < N_NODES) v = *(const int4*)&g_cnt[base];
    else {
        if (base + 0 < N_NODES) v.x = g_cnt[base + 0];
        if (base + 1 < N_NODES) v.y = g_cnt[base + 1];
        if (base + 2 < N_NODES) v.z = g_cnt[base + 2];
    }
    // dinv (degrees final here)
    if (base + 3 < N_NODES) {
        float4 dv;
        dv.x = rsqrtf((float)v.x + 1.0f);
        dv.y = rsqrtf((float)v.y + 1.0f);
        dv.z = rsqrtf((float)v.z + 1.0f);
        dv.w = rsqrtf((float)v.w + 1.0f);
        *(float4*)&g_dinv[base] = dv;
    } else {
        if (base + 0 < N_NODES) g_dinv[base + 0] = rsqrtf((float)v.x + 1.0f);
        if (base + 1 < N_NODES) g_dinv[base + 1] = rsqrtf((float)v.y + 1.0f);
        if (base + 2 < N_NODES) g_dinv[base + 2] = rsqrtf((float)v.z + 1.0f);
    }
    int tsum = v.x + v.y + v.z + v.w;
    int inc = tsum;
    #pragma unroll
    for (int o = 1; o < 32; o <<= 1) {
        int u = __shfl_up_sync(FULLM, inc, o);
        if (lane >= o) inc += u;
    }
    if (lane == 31) ws[warp] = inc;
    __syncthreads();
    if (warp == 0) {
        int w = (lane < 8) ? ws[lane] : 0;
        int wi = w;
        #pragma unroll
        for (int o = 1; o < 8; o <<= 1) {
            int u = __shfl_up_sync(FULLM, wi, o);
            if (lane >= o) wi += u;
        }
        if (lane < 8) ws[lane] = wi - w;          // exclusive warp base
        if (lane == 7) {
            stotal = wi;
            atomicExch(&g_state[blockIdx.x],
                       (1ULL << 62) | (unsigned long long)(unsigned int)wi);
        }
    }
    __syncthreads();
    if (t == 0) {
        int exc = 0;
        int p = (int)blockIdx.x - 1;
        while (p >= 0) {
            unsigned long long s;
            do { s = atomicAdd(&g_state[p], 0ULL); } while ((s >> 62) == 0ULL);
            exc += (int)(unsigned int)(s & 0xffffffffULL);
            if ((s >> 62) == 2ULL) break;
            p--;
        }
        sbase = exc;
        atomicExch(&g_state[blockIdx.x],
                   (2ULL << 62) | (unsigned long long)(unsigned int)(exc + stotal));
    }
    __syncthreads();
    int b = sbase + ws[warp] + inc - tsum;
    int4 o;
    o.x = b; o.y = b + v.x; o.z = o.y + v.y; o.w = o.z + v.z;
    if (base + 3 < N_NODES) *(int4*)&g_off[base] = o;
    else {
        if (base + 0 < N_NODES) g_off[base + 0] = o.x;
        if (base + 1 < N_NODES) g_off[base + 1] = o.y;
        if (base + 2 < N_NODES) g_off[base + 2] = o.z;
    }
}

// ---------------- y1 = dinv * (x @ W1): warp-per-4-nodes, f32x2 + transpose-reduce ----------------
__global__ void __launch_bounds__(256) k_mm1(const float* __restrict__ x,
                                             const float* __restrict__ W1) {
    __shared__ float sWt[8][512];     // transposed W1 (16 KB)
    int t = threadIdx.x;
    for (int i = t; i < 4096; i += 256) {
        int k = i >> 3, o = i & 7;    // read W1 coalesced
        sWt[o][k] = W1[i];
    }
    __syncthreads();

    int warp = t >> 5, lane = t & 31;
    int n0 = blockIdx.x * 32 + warp * 4;          // 4 nodes per warp
    if (n0 >= N_NODES) return;

    const float4* x4 = (const float4*)x;
    const float4* sWt4 = (const float4*)sWt;      // sWt4[o*128 + k4]

    int nn[4];
    #pragma unroll
    for (int m = 0; m < 4; m++) {
        int n = n0 + m;
        nn[m] = (n < N_NODES) ? n : (N_NODES - 1);
    }

    unsigned long long acc2[4][8];
    #pragma unroll
    for (int m = 0; m < 4; m++)
        #pragma unroll
        for (int o = 0; o < 8; o++) acc2[m][o] = 0ULL;

    #pragma unroll
    for (int q = 0; q < 4; q++) {
        int k4 = lane + 32 * q;
        unsigned long long wlo[8], whi[8];
        #pragma unroll
        for (int o = 0; o < 8; o++) {
            float4 wv = sWt4[o * 128 + k4];
            wlo[o] = pack2(wv.x, wv.y);
            whi[o] = pack2(wv.z, wv.w);
        }
        #pragma unroll
        for (int m = 0; m < 4; m++) {
            float4 xv = __ldg(&x4[(size_t)nn[m] * 128 + k4]);
            unsigned long long xa = pack2(xv.x, xv.y);
            unsigned long long xb = pack2(xv.z, xv.w);
            #pragma unroll
            for (int o = 0; o < 8; o++) {
                fma2v(acc2[m][o], xa, wlo[o]);
                fma2v(acc2[m][o], xb, whi[o]);
            }
        }
    }

    // unpack to 32 per-lane partials: v[m*8+o]
    float v[32];
    #pragma unroll
    for (int m = 0; m < 4; m++)
        #pragma unroll
        for (int o = 0; o < 8; o++) {
            float2 f = unpack2(acc2[m][o]);
            v[m * 8 + o] = f.x + f.y;
        }

    // transpose-reduce: after 5 stages, lane L holds sum over lanes of v[L]
    #pragma unroll
    for (int off = 16; off; off >>= 1) {
        bool hi = (lane & off) != 0;
        #pragma unroll
        for (int i = 0; i < 32; i++) {
            if (i >= off) continue;               // compile-time pruned: i < off
            float send = hi ? v[i] : v[i + off];
            float recv = __shfl_xor_sync(FULLM, send, off);
            v[i] = (hi ? v[i + off] : v[i]) + recv;
        }
    }

    // lane L has final sum for node n0 + (L>>3), output (L&7) -> coalesced store
    int n = n0 + (lane >> 3);
    if (n < N_NODES) {
        float di = g_dinv[n];
        g_y1[n * 8 + (lane & 7)] = v[0] * di;
    }
}

// ---------------- counting-sort placement (atomic cursor on g_off) ----------------
// After this kernel g_off[n] == end of bucket n; layers use e0 = g_off[n] - g_cnt[n].
__global__ void k_place() {
    int e = blockIdx.x * blockDim.x + threadIdx.x;
    if (e >= E_EDGES) return;
    int d = g_tdst[e];
    int pos = atomicAdd(&g_off[d], 1);
    g_esrc[pos] = g_tsrc[e];
}

// ---------------- Layer 1: agg(y1) -> relu -> y2 = dinv*(h1@W2) ----------------
__global__ void __launch_bounds__(256) k_layer1(const float* __restrict__ b1,
                                                const float* __restrict__ W2) {
    __shared__ float sW2[128];   // 8x16
    int t = threadIdx.x;
    if (t < 128) sW2[t] = W2[t];
    __syncthreads();
    int warp = t >> 5, lane = t & 31;
    int n = blockIdx.x * 8 + warp;
    if (n >= N_NODES) return;
    int end = g_off[n], cnt = g_cnt[n], e0 = end - cnt;
    int f = lane & 7;
    float acc = 0.f;
    for (int e = (lane >> 3); e < cnt; e += 4) {
        int s = g_esrc[e0 + e];
        acc += __ldg(&g_y1[s * 8 + f]);
    }
    acc += __shfl_down_sync(FULLM, acc, 16);
    acc += __shfl_down_sync(FULLM, acc, 8);
    float di = g_dinv[n];
    float h = 0.f;
    if (lane < 8) h = fmaxf(di * (acc + g_y1[n * 8 + lane]) + b1[lane], 0.f);
    float out = 0.f;
    int j = lane & 15;
    #pragma unroll
    for (int k = 0; k < 8; k++) {
        float hk = __shfl_sync(FULLM, h, k);
        out += hk * sW2[k * 16 + j];
    }
    if (lane < 16) g_y2[n * 16 + lane] = di * out;
}

// ---------------- Layer 2: agg(y2) -> relu -> y3 = dinv*(h2@W3), collapse to z ----------------
__global__ void __launch_bounds__(256) k_layer2(const float* __restrict__ b2,
                                                const float* __restrict__ W3,
                                                const float* __restrict__ Wfc) {
    __shared__ float sW3[512];   // 16x32
    __shared__ float sWfc[64];
    int t = threadIdx.x;
    for (int i = t; i < 512; i += 256) sW3[i] = W3[i];
    if (t < 64) sWfc[t] = Wfc[t];
    __syncthreads();
    int warp = t >> 5, lane = t & 31;
    int n = blockIdx.x * 8 + warp;
    if (n >= N_NODES) return;
    int end = g_off[n], cnt = g_cnt[n], e0 = end - cnt;
    int f = lane & 15;
    float acc = 0.f;
    for (int e = (lane >> 4); e < cnt; e += 2) {
        int s = g_esrc[e0 + e];
        acc += __ldg(&g_y2[s * 16 + f]);
    }
    acc += __shfl_down_sync(FULLM, acc, 16);
    float di = g_dinv[n];
    float h = 0.f;
    if (lane < 16) h = fmaxf(di * (acc + g_y2[n * 16 + lane]) + b2[lane], 0.f);
    float out = 0.f;
    #pragma unroll
    for (int k = 0; k < 16; k++) {
        float hk = __shfl_sync(FULLM, h, k);
        out += hk * sW3[k * 32 + lane];
    }
    float y3v = di * out;                       // y3[n][lane]
    float za = y3v * sWfc[lane];
    float zb = y3v * sWfc[32 + lane];
    #pragma unroll
    for (int o = 16; o; o >>= 1) {
        za += __shfl_xor_sync(FULLM, za, o);
        zb += __shfl_xor_sync(FULLM, zb, o);
    }
    if (lane == 0) g_z[n] = make_float2(za, zb);
}

// ---------------- Layer 3 (scalarized): sa/sb = dinv*(sum z[src] + z[n]) + cab ----------------
__global__ void __launch_bounds__(256) k_layer3() {
    int t = threadIdx.x;
    int warp = t >> 5, lane = t & 31;
    int n = blockIdx.x * 8 + warp;
    if (n >= N_NODES) return;
    int end = g_off[n], cnt = g_cnt[n], e0 = end - cnt;
    float ax = 0.f, ay = 0.f;
    for (int e = lane; e < cnt; e += 32) {
        int s = g_esrc[e0 + e];
        float2 z = __ldg(&g_z[s]);
        ax += z.x; ay += z.y;
    }
    #pragma unroll
    for (int o = 16; o; o >>= 1) {
        ax += __shfl_xor_sync(FULLM, ax, o);
        ay += __shfl_xor_sync(FULLM, ay, o);
    }
    if (lane == 0) {
        float di = g_dinv[n];
        float2 zn = g_z[n];
        g_sa[n] = di * (ax + zn.x) + g_cab.x;
        g_sb[n] = di * (ay + zn.y) + g_cab.y;
    }
}

// ---------------- Final: out[s] = sigmoid(sa[i] + sb[j] + bfc) ----------------
__global__ void __launch_bounds__(256) k_final(const void* __restrict__ smp,
                                               const float* __restrict__ bfc,
                                               float* __restrict__ out) {
    int s = blockIdx.x * 256 + threadIdx.x;
    if (s >= S_SAMP) return;
    long long i, j;
    if (g_flags[1]) {
        const int* p = (const int*)smp;
        i = p[2 * s]; j = p[2 * s + 1];
    } else {
        const long long* p = (const long long*)smp;
        i = p[2 * (size_t)s]; j = p[2 * (size_t)s + 1];
    }
    float v = __ldg(&g_sa[i]) + __ldg(&g_sb[j]) + __ldg(bfc);
    out[s] = 1.f / (1.f + __expf(-v));
}

// ---------------- launch ----------------
extern "C" void kernel_launch(void* const* d_in, const int* in_sizes, int n_in,
                              void* d_out, int out_size) {
    const float* x   = (const float*)d_in[0];
    const void*  ei  = d_in[1];
    const void*  smp = d_in[2];
    const float* W1  = (const float*)d_in[3];
    const float* b1  = (const float*)d_in[4];
    const float* W2  = (const float*)d_in[5];
    const float* b2  = (const float*)d_in[6];
    const float* W3  = (const float*)d_in[7];
    const float* b3  = (const float*)d_in[8];
    const float* Wfc = (const float*)d_in[9];
    const float* bfc = (const float*)d_in[10];
    float* out = (float*)d_out;

    const int nb_scan = (N_NODES + 1023) / 1024;   // 98

    k_init<<<(N_NODES + 255) / 256, 256>>>((const int*)ei, (const int*)smp, b3, Wfc);
    k_count<<<(E_EDGES + 255) / 256, 256>>>(ei);
    k_scan<<<nb_scan, 256>>>();
    k_mm1<<<(N_NODES + 31) / 32, 256>>>(x, W1);    // launch #4: profiled slot
    k_place<<<(E_EDGES + 255) / 256, 256>>>();
    k_layer1<<<(N_NODES + 7) / 8, 256>>>(b1, W2);
    k_layer2<<<(N_NODES + 7) / 8, 256>>>(b2, W3, Wfc);
    k_layer3<<<(N_NODES + 7) / 8, 256>>>();
    k_final<<<(S_SAMP + 255) / 256, 256>>>(smp, bfc, out);
}

// round 10
// speedup vs baseline: 1.4065x; 1.0836x over previous
#include <cuda_runtime.h>
#include <math.h>

#define N_NODES 100000
#define E_EDGES 3200000
#define S_SAMP  1000000
#define FULLM   0xffffffffu

// ---------------- device scratch (static: no allocations allowed) ----------------
__device__ __align__(16) int   g_cnt[N_NODES];
__device__ __align__(16) int   g_off[N_NODES];
__device__ unsigned long long g_state[128];   // decoupled-lookback: status<<62 | value
__device__ int   g_tsrc[E_EDGES];
__device__ int   g_tdst[E_EDGES];
__device__ int   g_esrc[E_EDGES];             // src sorted by dst (CSR payload)
__device__ __align__(16) float g_dinv[N_NODES];
__device__ __align__(16) float g_y1[N_NODES * 8];
__device__ __align__(16) float g_y2[N_NODES * 16];
__device__ __align__(8)  float2 g_z[N_NODES]; // (y3 . Wa, y3 . Wb)
__device__ float g_sa[N_NODES];
__device__ float g_sb[N_NODES];
__device__ float2 g_cab;                      // (b3 . Wa, b3 . Wb)
__device__ int g_flags[2];                    // [0]: edge_index is int32, [1]: samples is int32

// ---------------- init: zero counts + scan state + dtype detection + head constants ----------------
__global__ void k_init(const int* __restrict__ ei, const int* __restrict__ sm,
                       const float* __restrict__ b3, const float* __restrict__ Wfc) {
    int i = blockIdx.x * blockDim.x + threadIdx.x;
    if (i < N_NODES) g_cnt[i] = 0;
    if (i < 128) g_state[i] = 0ULL;
    if (blockIdx.x == 0) {
        if (threadIdx.x == 0) {
            g_flags[0] = 0; g_flags[1] = 0;
            float ca = 0.f, cb = 0.f;
            #pragma unroll
            for (int f = 0; f < 32; f++) { ca += b3[f] * Wfc[f]; cb += b3[f] * Wfc[32 + f]; }
            g_cab = make_float2(ca, cb);
        }
        __syncthreads();
        int e_nz = 0, s_nz = 0;
        for (int k = threadIdx.x; k < 1024; k += 256) {
            if (ei[2 * k + 1] != 0) e_nz = 1;
            if (sm[2 * k + 1] != 0) s_nz = 1;
        }
        if (e_nz) atomicOr(&g_flags[0], 1);
        if (s_nz) atomicOr(&g_flags[1], 1);
    }
}

// ---------------- edge preprocessing: count + stash as int32 ----------------
__global__ void k_count(const void* __restrict__ eip) {
    int e = blockIdx.x * blockDim.x + threadIdx.x;
    if (e >= E_EDGES) return;
    int s, d;
    if (g_flags[0]) {
        const int* p = (const int*)eip;
        s = p[e]; d = p[E_EDGES + e];
    } else {
        const long long* p = (const long long*)eip;
        s = (int)p[e]; d = (int)p[(size_t)E_EDGES + e];
    }
    g_tsrc[e] = s; g_tdst[e] = d;
    atomicAdd(&g_cnt[d], 1);
}

// ---------------- single-pass scan (decoupled lookback) + dinv ----------------
__global__ void __launch_bounds__(256) k_scan() {
    __shared__ int ws[8];
    __shared__ int stotal;
    __shared__ int sbase;
    int t = threadIdx.x, lane = t & 31, warp = t >> 5;
    int base = blockIdx.x * 1024 + t * 4;
    int4 v = make_int4(0, 0, 0, 0);
    if (base + 3 < N_NODES) v = *(const int4*)&g_cnt[base];
    else {
        if (base + 0 < N_NODES) v.x = g_cnt[base + 0];
        if (base + 1 < N_NODES) v.y = g_cnt[base + 1];
        if (base + 2 < N_NODES) v.z = g_cnt[base + 2];
    }
    // dinv (degrees final here)
    if (base + 3 < N_NODES) {
        float4 dv;
        dv.x = rsqrtf((float)v.x + 1.0f);
        dv.y = rsqrtf((float)v.y + 1.0f);
        dv.z = rsqrtf((float)v.z + 1.0f);
        dv.w = rsqrtf((float)v.w + 1.0f);
        *(float4*)&g_dinv[base] = dv;
    } else {
        if (base + 0 < N_NODES) g_dinv[base + 0] = rsqrtf((float)v.x + 1.0f);
        if (base + 1 < N_NODES) g_dinv[base + 1] = rsqrtf((float)v.y + 1.0f);
        if (base + 2 < N_NODES) g_dinv[base + 2] = rsqrtf((float)v.z + 1.0f);
    }
    int tsum = v.x + v.y + v.z + v.w;
    int inc = tsum;
    #pragma unroll
    for (int o = 1; o < 32; o <<= 1) {
        int u = __shfl_up_sync(FULLM, inc, o);
        if (lane >= o) inc += u;
    }
    if (lane == 31) ws[warp] = inc;
    __syncthreads();
    if (warp == 0) {
        int w = (lane < 8) ? ws[lane] : 0;
        int wi = w;
        #pragma unroll
        for (int o = 1; o < 8; o <<= 1) {
            int u = __shfl_up_sync(FULLM, wi, o);
            if (lane >= o) wi += u;
        }
        if (lane < 8) ws[lane] = wi - w;          // exclusive warp base
        if (lane == 7) {
            stotal = wi;
            atomicExch(&g_state[blockIdx.x],
                       (1ULL << 62) | (unsigned long long)(unsigned int)wi);
        }
    }
    __syncthreads();
    if (t == 0) {
        int exc = 0;
        int p = (int)blockIdx.x - 1;
        while (p >= 0) {
            unsigned long long s;
            do { s = atomicAdd(&g_state[p], 0ULL); } while ((s >> 62) == 0ULL);
            exc += (int)(unsigned int)(s & 0xffffffffULL);
            if ((s >> 62) == 2ULL) break;
            p--;
        }
        sbase = exc;
        atomicExch(&g_state[blockIdx.x],
                   (2ULL << 62) | (unsigned long long)(unsigned int)(exc + stotal));
    }
    __syncthreads();
    int b = sbase + ws[warp] + inc - tsum;
    int4 o;
    o.x = b; o.y = b + v.x; o.z = o.y + v.y; o.w = o.z + v.z;
    if (base + 3 < N_NODES) *(int4*)&g_off[base] = o;
    else {
        if (base + 0 < N_NODES) g_off[base + 0] = o.x;
        if (base + 1 < N_NODES) g_off[base + 1] = o.y;
        if (base + 2 < N_NODES) g_off[base + 2] = o.z;
    }
}

// ---------------- y1 = dinv * (x @ W1): warp-per-4-nodes, lean regs + transpose-reduce ----------------
__global__ void __launch_bounds__(256, 3) k_mm1(const float* __restrict__ x,
                                                const float* __restrict__ W1) {
    __shared__ float sWt[8][512];     // transposed W1 (16 KB)
    int t = threadIdx.x;
    for (int i = t; i < 4096; i += 256) {
        int k = i >> 3, o = i & 7;    // read W1 coalesced
        sWt[o][k] = W1[i];
    }
    __syncthreads();

    int warp = t >> 5, lane = t & 31;
    int n0 = blockIdx.x * 32 + warp * 4;          // 4 nodes per warp
    if (n0 >= N_NODES) return;

    const float4* x4 = (const float4*)x;
    const float4* sWt4 = (const float4*)sWt;      // sWt4[o*128 + k4]

    int nn[4];
    #pragma unroll
    for (int m = 0; m < 4; m++) {
        int n = n0 + m;
        nn[m] = (n < N_NODES) ? n : (N_NODES - 1);
    }

    // acc[m*8+o]; transpose-reduce later operates in place on these 32 regs
    float acc[32];
    #pragma unroll
    for (int i = 0; i < 32; i++) acc[i] = 0.f;

    #pragma unroll
    for (int q = 0; q < 4; q++) {
        int k4 = lane + 32 * q;
        float4 xv[4];
        #pragma unroll
        for (int m = 0; m < 4; m++)
            xv[m] = __ldg(&x4[(size_t)nn[m] * 128 + k4]);
        #pragma unroll
        for (int o = 0; o < 8; o++) {
            float4 w = sWt4[o * 128 + k4];        // one weight vec reused by 4 nodes
            #pragma unroll
            for (int m = 0; m < 4; m++) {
                float a = acc[m * 8 + o];
                a = fmaf(xv[m].x, w.x, a);
                a = fmaf(xv[m].y, w.y, a);
                a = fmaf(xv[m].z, w.z, a);
                a = fmaf(xv[m].w, w.w, a);
                acc[m * 8 + o] = a;
            }
        }
    }

    // transpose-reduce: after 5 stages, lane L holds total sum of acc[L]
    #pragma unroll
    for (int off = 16; off; off >>= 1) {
        bool hi = (lane & off) != 0;
        #pragma unroll
        for (int i = 0; i < 32; i++) {
            if (i >= off) continue;               // compile-time pruned: i < off
            float send = hi ? acc[i] : acc[i + off];
            float recv = __shfl_xor_sync(FULLM, send, off);
            acc[i] = (hi ? acc[i + off] : acc[i]) + recv;
        }
    }

    // lane L has final sum for node n0 + (L>>3), output (L&7) -> coalesced 128B store
    int n = n0 + (lane >> 3);
    if (n < N_NODES) {
        float di = g_dinv[n];
        g_y1[n * 8 + (lane & 7)] = acc[0] * di;
    }
}

// ---------------- counting-sort placement (atomic cursor on g_off) ----------------
// After this kernel g_off[n] == end of bucket n; layers use e0 = g_off[n] - g_cnt[n].
__global__ void k_place() {
    int e = blockIdx.x * blockDim.x + threadIdx.x;
    if (e >= E_EDGES) return;
    int d = g_tdst[e];
    int pos = atomicAdd(&g_off[d], 1);
    g_esrc[pos] = g_tsrc[e];
}

// ---------------- Layer 1: agg(y1) -> relu -> y2 = dinv*(h1@W2) ----------------
__global__ void __launch_bounds__(256) k_layer1(const float* __restrict__ b1,
                                                const float* __restrict__ W2) {
    __shared__ float sW2[128];   // 8x16
    int t = threadIdx.x;
    if (t < 128) sW2[t] = W2[t];
    __syncthreads();
    int warp = t >> 5, lane = t & 31;
    int n = blockIdx.x * 8 + warp;
    if (n >= N_NODES) return;
    int end = g_off[n], cnt = g_cnt[n], e0 = end - cnt;
    int f = lane & 7;
    float acc = 0.f;
    for (int e = (lane >> 3); e < cnt; e += 4) {
        int s = g_esrc[e0 + e];
        acc += __ldg(&g_y1[s * 8 + f]);
    }
    acc += __shfl_down_sync(FULLM, acc, 16);
    acc += __shfl_down_sync(FULLM, acc, 8);
    float di = g_dinv[n];
    float h = 0.f;
    if (lane < 8) h = fmaxf(di * (acc + g_y1[n * 8 + lane]) + b1[lane], 0.f);
    float out = 0.f;
    int j = lane & 15;
    #pragma unroll
    for (int k = 0; k < 8; k++) {
        float hk = __shfl_sync(FULLM, h, k);
        out += hk * sW2[k * 16 + j];
    }
    if (lane < 16) g_y2[n * 16 + lane] = di * out;
}

// ---------------- Layer 2: agg(y2) -> relu -> y3 = dinv*(h2@W3), collapse to z ----------------
__global__ void __launch_bounds__(256) k_layer2(const float* __restrict__ b2,
                                                const float* __restrict__ W3,
                                                const float* __restrict__ Wfc) {
    __shared__ float sW3[512];   // 16x32
    __shared__ float sWfc[64];
    int t = threadIdx.x;
    for (int i = t; i < 512; i += 256) sW3[i] = W3[i];
    if (t < 64) sWfc[t] = Wfc[t];
    __syncthreads();
    int warp = t >> 5, lane = t & 31;
    int n = blockIdx.x * 8 + warp;
    if (n >= N_NODES) return;
    int end = g_off[n], cnt = g_cnt[n], e0 = end - cnt;
    int f = lane & 15;
    float acc = 0.f;
    for (int e = (lane >> 4); e < cnt; e += 2) {
        int s = g_esrc[e0 + e];
        acc += __ldg(&g_y2[s * 16 + f]);
    }
    acc += __shfl_down_sync(FULLM, acc, 16);
    float di = g_dinv[n];
    float h = 0.f;
    if (lane < 16) h = fmaxf(di * (acc + g_y2[n * 16 + lane]) + b2[lane], 0.f);
    float out = 0.f;
    #pragma unroll
    for (int k = 0; k < 16; k++) {
        float hk = __shfl_sync(FULLM, h, k);
        out += hk * sW3[k * 32 + lane];
    }
    float y3v = di * out;                       // y3[n][lane]
    float za = y3v * sWfc[lane];
    float zb = y3v * sWfc[32 + lane];
    #pragma unroll
    for (int o = 16; o; o >>= 1) {
        za += __shfl_xor_sync(FULLM, za, o);
        zb += __shfl_xor_sync(FULLM, zb, o);
    }
    if (lane == 0) g_z[n] = make_float2(za, zb);
}

// ---------------- Layer 3 (scalarized): sa/sb = dinv*(sum z[src] + z[n]) + cab ----------------
__global__ void __launch_bounds__(256) k_layer3() {
    int t = threadIdx.x;
    int warp = t >> 5, lane = t & 31;
    int n = blockIdx.x * 8 + warp;
    if (n >= N_NODES) return;
    int end = g_off[n], cnt = g_cnt[n], e0 = end - cnt;
    float ax = 0.f, ay = 0.f;
    for (int e = lane; e < cnt; e += 32) {
        int s = g_esrc[e0 + e];
        float2 z = __ldg(&g_z[s]);
        ax += z.x; ay += z.y;
    }
    #pragma unroll
    for (int o = 16; o; o >>= 1) {
        ax += __shfl_xor_sync(FULLM, ax, o);
        ay += __shfl_xor_sync(FULLM, ay, o);
    }
    if (lane == 0) {
        float di = g_dinv[n];
        float2 zn = g_z[n];
        g_sa[n] = di * (ax + zn.x) + g_cab.x;
        g_sb[n] = di * (ay + zn.y) + g_cab.y;
    }
}

// ---------------- Final: out[s] = sigmoid(sa[i] + sb[j] + bfc) ----------------
__global__ void __launch_bounds__(256) k_final(const void* __restrict__ smp,
                                               const float* __restrict__ bfc,
                                               float* __restrict__ out) {
    int s = blockIdx.x * 256 + threadIdx.x;
    if (s >= S_SAMP) return;
    long long i, j;
    if (g_flags[1]) {
        const int* p = (const int*)smp;
        i = p[2 * s]; j = p[2 * s + 1];
    } else {
        const long long* p = (const long long*)smp;
        i = p[2 * (size_t)s]; j = p[2 * (size_t)s + 1];
    }
    float v = __ldg(&g_sa[i]) + __ldg(&g_sb[j]) + __ldg(bfc);
    out[s] = 1.f / (1.f + __expf(-v));
}

// ---------------- launch ----------------
extern "C" void kernel_launch(void* const* d_in, const int* in_sizes, int n_in,
                              void* d_out, int out_size) {
    const float* x   = (const float*)d_in[0];
    const void*  ei  = d_in[1];
    const void*  smp = d_in[2];
    const float* W1  = (const float*)d_in[3];
    const float* b1  = (const float*)d_in[4];
    const float* W2  = (const float*)d_in[5];
    const float* b2  = (const float*)d_in[6];
    const float* W3  = (const float*)d_in[7];
    const float* b3  = (const float*)d_in[8];
    const float* Wfc = (const float*)d_in[9];
    const float* bfc = (const float*)d_in[10];
    float* out = (float*)d_out;

    const int nb_scan = (N_NODES + 1023) / 1024;   // 98

    k_init<<<(N_NODES + 255) / 256, 256>>>((const int*)ei, (const int*)smp, b3, Wfc);
    k_count<<<(E_EDGES + 255) / 256, 256>>>(ei);
    k_scan<<<nb_scan, 256>>>();
    k_mm1<<<(N_NODES + 31) / 32, 256>>>(x, W1);    // launch #4: profiled slot
    k_place<<<(E_EDGES + 255) / 256, 256>>>();
    k_layer1<<<(N_NODES + 7) / 8, 256>>>(b1, W2);
    k_layer2<<<(N_NODES + 7) / 8, 256>>>(b2, W3, Wfc);
    k_layer3<<<(N_NODES + 7) / 8, 256>>>();
    k_final<<<(S_SAMP + 255) / 256, 256>>>(smp, bfc, out);
}